// round 1
// baseline (speedup 1.0000x reference)
#include <cuda_runtime.h>
#include <math.h>

#define NEXP 64
#define KSEL 8
#define DDIM 1024
#define MTILE 128
#define KC 32
#define MAXBLK 512

// Deterministic per-block partial sums of softmax gate weights (per expert).
__device__ float g_part[MAXBLK * NEXP];

__global__ __launch_bounds__(256) void gate_kernel(
    const float* __restrict__ x, const float* __restrict__ w,
    const float* __restrict__ nw, const float* __restrict__ noise,
    float* __restrict__ out_w, float* __restrict__ out_ids)
{
    // Union: GEMM tiles (As 32x132 + Bs 32x68 = 6400 floats) overlap the
    // epilogue logits buffer L[128][65] = 8320 floats.
    __shared__ __align__(16) float Lbuf[128 * 65];
    __shared__ float partial[NEXP];
    __shared__ float rowM[128], rowSinv[128];
    __shared__ float nw_s[NEXP];

    float (*As)[132] = reinterpret_cast<float(*)[132]>(Lbuf);
    float (*Bs)[68]  = reinterpret_cast<float(*)[68]>(Lbuf + 32 * 132);

    const int tid = threadIdx.x;
    const int tx = tid & 15;      // expert group (4 experts each)
    const int ty = tid >> 4;      // row group (8 rows each)
    const int base = blockIdx.x * MTILE;

    if (tid < NEXP) nw_s[tid] = nw[tid];

    float acc[8][4];
#pragma unroll
    for (int r = 0; r < 8; r++)
#pragma unroll
        for (int c = 0; c < 4; c++) acc[r][c] = 0.f;

    for (int k0 = 0; k0 < DDIM; k0 += KC) {
        __syncthreads();
        // Load A tile [128 rows x 32 k] transposed into As[k][row]
#pragma unroll
        for (int i = 0; i < 4; i++) {
            int fid = tid + i * 256;
            int arow = fid >> 3;
            int ac4 = fid & 7;
            float4 v = *reinterpret_cast<const float4*>(
                &x[(size_t)(base + arow) * DDIM + k0 + ac4 * 4]);
            As[ac4 * 4 + 0][arow] = v.x;
            As[ac4 * 4 + 1][arow] = v.y;
            As[ac4 * 4 + 2][arow] = v.z;
            As[ac4 * 4 + 3][arow] = v.w;
        }
        // Load B tile [64 experts x 32 k] transposed into Bs[k][e]
#pragma unroll
        for (int i = 0; i < 2; i++) {
            int fid = tid + i * 256;
            int e = fid >> 3;
            int kc4 = fid & 7;
            float4 v = *reinterpret_cast<const float4*>(
                &w[(size_t)e * DDIM + k0 + kc4 * 4]);
            Bs[kc4 * 4 + 0][e] = v.x;
            Bs[kc4 * 4 + 1][e] = v.y;
            Bs[kc4 * 4 + 2][e] = v.z;
            Bs[kc4 * 4 + 3][e] = v.w;
        }
        __syncthreads();
#pragma unroll
        for (int k = 0; k < KC; k++) {
            float4 a0 = *reinterpret_cast<float4*>(&As[k][ty * 8]);
            float4 a1 = *reinterpret_cast<float4*>(&As[k][ty * 8 + 4]);
            float4 b  = *reinterpret_cast<float4*>(&Bs[k][tx * 4]);
            float av[8] = {a0.x, a0.y, a0.z, a0.w, a1.x, a1.y, a1.z, a1.w};
            float bv[4] = {b.x, b.y, b.z, b.w};
#pragma unroll
            for (int r = 0; r < 8; r++)
#pragma unroll
                for (int c = 0; c < 4; c++)
                    acc[r][c] = fmaf(av[r], bv[c], acc[r][c]);
        }
    }
    __syncthreads();  // GEMM tiles dead; Lbuf becomes logits [128][65]

#pragma unroll
    for (int r = 0; r < 8; r++)
#pragma unroll
        for (int c = 0; c < 4; c++)
            Lbuf[(ty * 8 + r) * 65 + tx * 4 + c] = acc[r][c];
    if (tid >= 128 && tid < 128 + NEXP) partial[tid - 128] = 0.f;
    __syncthreads();

    // Pass 1: dense softmax stats per row (threads 0..127, one row each)
    if (tid < 128) {
        float m = -INFINITY;
        for (int e = 0; e < NEXP; e++) m = fmaxf(m, Lbuf[tid * 65 + e]);
        float s = 0.f;
        for (int e = 0; e < NEXP; e++) s += expf(Lbuf[tid * 65 + e] - m);
        rowM[tid] = m;
        rowSinv[tid] = 1.f / s;
    }
    __syncthreads();

    // Pass 2: per-expert partial sums of gate weights (for load-balance mean)
    {
        int e = tid & 63;
        int grp = tid >> 6;  // 4 groups x 32 rows
        float a = 0.f;
        for (int r = grp * 32; r < grp * 32 + 32; r++)
            a += expf(Lbuf[r * 65 + e] - rowM[r]) * rowSinv[r];
        atomicAdd(&partial[e], a);  // smem only, 4 adders per address
    }
    __syncthreads();
    if (tid < NEXP) g_part[blockIdx.x * NEXP + tid] = partial[tid];

    // Add noise in place: L becomes noisy logits (coalesced noise read)
    for (int idx = tid; idx < 128 * 64; idx += 256) {
        int r = idx >> 6, e = idx & 63;
        Lbuf[r * 65 + e] += noise[(size_t)(base + r) * 64 + e] * nw_s[e];
    }
    __syncthreads();

    // Top-8 per row, sparse softmax (threads 0..127)
    if (tid < 128) {
        int r = tid;
        float best[KSEL];
        int bid[KSEL];
        unsigned long long used = 0ull;
#pragma unroll
        for (int k = 0; k < KSEL; k++) {
            float mv = -INFINITY;
            int mi = 0;
            for (int e = 0; e < NEXP; e++) {
                float v = Lbuf[r * 65 + e];
                bool ok = !((used >> e) & 1ull);
                if (ok && v > mv) { mv = v; mi = e; }
            }
            used |= 1ull << mi;
            best[k] = mv;
            bid[k] = mi;
        }
        float m0 = best[0];
        float s = 0.f;
#pragma unroll
        for (int k = 0; k < KSEL; k++) s += __expf(best[k] - m0);
        float inv = 1.f / s;
        for (int e = 0; e < NEXP; e++) Lbuf[r * 65 + e] = 0.f;
#pragma unroll
        for (int k = 0; k < KSEL; k++)
            Lbuf[r * 65 + bid[k]] = __expf(best[k] - m0) * inv;
#pragma unroll
        for (int k = 0; k < KSEL; k++)
            out_ids[(size_t)(base + r) * KSEL + k] = (float)bid[k];
    }
    __syncthreads();

    // Coalesced store of sparse gate weights
    for (int idx = tid; idx < 128 * 64; idx += 256) {
        int r = idx >> 6, e = idx & 63;
        out_w[(size_t)(base + r) * 64 + e] = Lbuf[r * 65 + e];
    }
}

__global__ void loss_kernel(int nBlocks, int N, float* __restrict__ out_loss)
{
    __shared__ double red[NEXP];
    int e = threadIdx.x;
    double s = 0.0;
    for (int b = 0; b < nBlocks; b++) s += (double)g_part[b * NEXP + e];
    double d = s / (double)N - 1.0 / (double)NEXP;
    red[e] = d * d;
    __syncthreads();
    for (int off = 32; off > 0; off >>= 1) {
        if (e < off) red[e] += red[e + off];
        __syncthreads();
    }
    if (e == 0) *out_loss = (float)(red[0] / (double)NEXP * 0.01);
}

extern "C" void kernel_launch(void* const* d_in, const int* in_sizes, int n_in,
                              void* d_out, int out_size)
{
    const float* x     = (const float*)d_in[0];  // [N, 1024]
    const float* w     = (const float*)d_in[1];  // [64, 1024]
    const float* nw    = (const float*)d_in[2];  // [64]
    const float* noise = (const float*)d_in[3];  // [N, 64]

    int N = in_sizes[3] / NEXP;
    int nBlocks = N / MTILE;

    float* out      = (float*)d_out;
    float* out_w    = out;                                  // [N, 64]
    float* out_ids  = out + (size_t)N * NEXP;               // [N, 8] as float
    float* out_loss = out + (size_t)N * NEXP + (size_t)N * KSEL;  // [1]

    gate_kernel<<<nBlocks, 256>>>(x, w, nw, noise, out_w, out_ids);
    loss_kernel<<<1, NEXP>>>(nBlocks, N, out_loss);
}

// round 6
// speedup vs baseline: 1.3445x; 1.3445x over previous
#include <cuda_runtime.h>
#include <cuda_fp16.h>
#include <math.h>
#include <stdint.h>

#define NEXP 64
#define KSEL 8
#define DDIM 1024
#define MTILE 128
#define NCHUNK 32          // K chunks of 32 (2 mma k-steps of 16)
#define MAXBLK 512
#define S11 2048.0f               // 2^11
#define I11 4.8828125e-4f         // 2^-11

__device__ float g_part[MAXBLK * NEXP];

__device__ __forceinline__ uint32_t h2u(half2 h) {
    return *reinterpret_cast<uint32_t*>(&h);
}

// 2-level split: v = h + l*2^-11 + r, |r| ~ 2^-24 |v|
__device__ __forceinline__ void split2(float2 v, uint32_t& h, uint32_t& l) {
    half2 hh = __float22half2_rn(v);
    float2 hb = __half22float2(hh);
    half2 ll = __float22half2_rn(
        make_float2((v.x - hb.x) * S11, (v.y - hb.y) * S11));
    h = h2u(hh);
    l = h2u(ll);
}

// chained accumulate (used only for the scaled correction terms)
#define MMA_F16_ACC(cc, a, b0, b1)                                             \
    asm volatile(                                                              \
        "mma.sync.aligned.m16n8k16.row.col.f32.f16.f16.f32 "                   \
        "{%0,%1,%2,%3},{%4,%5,%6,%7},{%8,%9},{%0,%1,%2,%3};"                   \
        : "+f"((cc)[0]), "+f"((cc)[1]), "+f"((cc)[2]), "+f"((cc)[3])           \
        : "r"((a)[0]), "r"((a)[1]), "r"((a)[2]), "r"((a)[3]),                  \
          "r"(b0), "r"(b1))

// fresh accumulator: D = A*B + 0 (C = zero regs, D != C) — avoids the
// tensor-core RZ bias of long accumulation chains
#define MMA_F16_NEW(dd, a, b0, b1)                                             \
    asm volatile(                                                              \
        "mma.sync.aligned.m16n8k16.row.col.f32.f16.f16.f32 "                   \
        "{%0,%1,%2,%3},{%4,%5,%6,%7},{%8,%9},{%10,%11,%12,%13};"               \
        : "=f"((dd)[0]), "=f"((dd)[1]), "=f"((dd)[2]), "=f"((dd)[3])           \
        : "r"((a)[0]), "r"((a)[1]), "r"((a)[2]), "r"((a)[3]),                  \
          "r"(b0), "r"(b1),                                                    \
          "f"(0.0f), "f"(0.0f), "f"(0.0f), "f"(0.0f))

// B staging layout (u32 words): [st2][s2][comp2][tile8][lane32][slot2]
#define BOFF(st, s, c, t, ln, sl) \
    (((((st) * 2 + (s)) * 2 + (c)) * 8 + (t)) * 64 + (ln) * 2 + (sl))

__global__ void __launch_bounds__(512) gate_kernel(
    const float* __restrict__ x, const float* __restrict__ w,
    const float* __restrict__ nw, const float* __restrict__ noise,
    float* __restrict__ out_w, float* __restrict__ out_ids)
{
    // Union: B staging (4096 u32) <-> epilogue canvas L[128][65] (8320 f32)
    __shared__ __align__(16) float U[8320];
    __shared__ float nw_s[NEXP];
    __shared__ float wsum[4][NEXP];
    uint32_t* const UB = reinterpret_cast<uint32_t*>(U);

    const int tid    = threadIdx.x;
    const int wid    = tid >> 5;
    const int lane   = tid & 31;
    const int quad   = lane & 3;
    const int r0     = lane >> 2;
    const int rowgrp = wid >> 1;    // 0..7 -> rows rowgrp*16..+15
    const int eg     = wid & 1;     // expert half: tiles eg*4..eg*4+3
    const int base   = blockIdx.x * MTILE;

    if (tid < NEXP) nw_s[tid] = nw[tid];

    const float* pA  = x + (size_t)(base + rowgrp * 16 + r0) * DDIM + quad * 2;
    const float* pA8 = pA + 8 * DDIM;

    float c0[4][4], c1[4][4];
#pragma unroll
    for (int t = 0; t < 4; t++)
#pragma unroll
        for (int i = 0; i < 4; i++) { c0[t][i] = 0.f; c1[t][i] = 0.f; }

#define WLD(ch) (*(const float4*)(w + (size_t)(tid >> 3) * DDIM + (ch) * 32 + (tid & 7) * 4))

// Stage one float4 of w (expert n = tid>>3, k = (tid&7)*4..+3) as h/l half2s
#define STSB(st, v) do {                                                       \
    int _n = tid >> 3, _j4 = tid & 7;                                          \
    int _s = _j4 >> 2, _k0 = (_j4 & 3) * 4;                                    \
    int _tile = _n >> 3, _lb = (_n & 7) * 4;                                   \
    uint32_t _h, _l;                                                           \
    int _sl0 = _k0 >> 3, _q0 = (_k0 & 7) >> 1;                                 \
    split2(make_float2((v).x, (v).y), _h, _l);                                 \
    UB[BOFF(st, _s, 0, _tile, _lb + _q0, _sl0)] = _h;                          \
    UB[BOFF(st, _s, 1, _tile, _lb + _q0, _sl0)] = _l;                          \
    int _k1 = _k0 + 2, _sl1 = _k1 >> 3, _q1 = (_k1 & 7) >> 1;                  \
    split2(make_float2((v).z, (v).w), _h, _l);                                 \
    UB[BOFF(st, _s, 0, _tile, _lb + _q1, _sl1)] = _h;                          \
    UB[BOFF(st, _s, 1, _tile, _lb + _q1, _sl1)] = _l;                          \
} while (0)

// Raw A chunk: per kstep s, 4 float2 pairs in fragment order (a0,a1,a2,a3)
#define LDA(ch, a) do {                                                        \
    _Pragma("unroll")                                                          \
    for (int _s2 = 0; _s2 < 2; _s2++) {                                        \
        *(float2*)&(a)[_s2 * 8 + 0] = *(const float2*)(pA  + (ch) * 32 + _s2 * 16);     \
        *(float2*)&(a)[_s2 * 8 + 2] = *(const float2*)(pA8 + (ch) * 32 + _s2 * 16);     \
        *(float2*)&(a)[_s2 * 8 + 4] = *(const float2*)(pA  + (ch) * 32 + _s2 * 16 + 8); \
        *(float2*)&(a)[_s2 * 8 + 6] = *(const float2*)(pA8 + (ch) * 32 + _s2 * 16 + 8); \
    }                                                                          \
} while (0)

#define CHUNK_BODY(ch, stR, aC, aN) do {                                       \
    if ((ch) + 1 < NCHUNK) STSB((stR) ^ 1, wv);                                \
    if ((ch) + 2 < NCHUNK) wv = WLD((ch) + 2);                                 \
    if ((ch) + 1 < NCHUNK) LDA((ch) + 1, aN);                                  \
    _Pragma("unroll")                                                          \
    for (int _s = 0; _s < 2; _s++) {                                           \
        uint32_t ah[4], al[4];                                                 \
        _Pragma("unroll")                                                      \
        for (int _i = 0; _i < 4; _i++)                                         \
            split2(*(float2*)&(aC)[_s * 8 + _i * 2], ah[_i], al[_i]);          \
        _Pragma("unroll")                                                      \
        for (int _t = 0; _t < 4; _t++) {                                       \
            const uint32_t _bb = BOFF(stR, _s, 0, eg * 4 + _t, lane, 0);       \
            uint2 bh = *(const uint2*)(UB + _bb);                              \
            uint2 bl = *(const uint2*)(UB + _bb + 512);                        \
            float dd[4];                                                       \
            MMA_F16_NEW(dd, ah, bh.x, bh.y);                                   \
            MMA_F16_ACC(c1[_t], ah, bl.x, bl.y);                               \
            MMA_F16_ACC(c1[_t], al, bh.x, bh.y);                               \
            c0[_t][0] += dd[0];                                                \
            c0[_t][1] += dd[1];                                                \
            c0[_t][2] += dd[2];                                                \
            c0[_t][3] += dd[3];                                                \
        }                                                                      \
    }                                                                          \
    __syncthreads();                                                           \
} while (0)

    // ---- prologue ----
    float4 wv = WLD(0);
    STSB(0, wv);
    wv = WLD(1);
    float aCur[16], aNxt[16];
    LDA(0, aCur);
    __syncthreads();

    // ---- main loop, ping-pong unrolled by 2 ----
#pragma unroll 1
    for (int cc = 0; cc < NCHUNK; cc += 2) {
        CHUNK_BODY(cc, 0, aCur, aNxt);
        CHUNK_BODY(cc + 1, 1, aNxt, aCur);
    }

    // ---- combine levels, dump to L[128][65] ----
    {
        int rA = rowgrp * 16 + r0;
#pragma unroll
        for (int t = 0; t < 4; t++) {
            int cb = (eg * 4 + t) * 8 + 2 * quad;
#pragma unroll
            for (int i = 0; i < 4; i++) {
                float v = fmaf(c1[t][i], I11, c0[t][i]);
                int rr = rA + (i >> 1) * 8;
                U[rr * 65 + cb + (i & 1)] = v;
            }
        }
    }
    __syncthreads();

    // ---- epilogue: threads 0..127 own one row each ----
    if (tid < 128) {
        const int r = tid;
        float L[64];
#pragma unroll
        for (int e = 0; e < 64; e++) L[e] = U[r * 65 + e];

        float m = -INFINITY;
#pragma unroll
        for (int e = 0; e < 64; e++) m = fmaxf(m, L[e]);
        float s = 0.f;
#pragma unroll
        for (int e = 0; e < 64; e++) s += __expf(L[e] - m);
        float sinv = 1.f / s;

        // per-expert column sums over this warp's 32 rows (deterministic)
#pragma unroll
        for (int e = 0; e < 64; e++) {
            float v = __expf(L[e] - m) * sinv;
            v += __shfl_xor_sync(0xffffffffu, v, 16);
            v += __shfl_xor_sync(0xffffffffu, v, 8);
            v += __shfl_xor_sync(0xffffffffu, v, 4);
            v += __shfl_xor_sync(0xffffffffu, v, 2);
            v += __shfl_xor_sync(0xffffffffu, v, 1);
            if ((e & 31) == lane) wsum[wid][e] = v;
        }

        // noisy logits
        const float4* np = (const float4*)(noise + (size_t)(base + r) * NEXP);
#pragma unroll
        for (int q = 0; q < 16; q++) {
            float4 nv = np[q];
            L[q * 4 + 0] = fmaf(nv.x, nw_s[q * 4 + 0], L[q * 4 + 0]);
            L[q * 4 + 1] = fmaf(nv.y, nw_s[q * 4 + 1], L[q * 4 + 1]);
            L[q * 4 + 2] = fmaf(nv.z, nw_s[q * 4 + 2], L[q * 4 + 2]);
            L[q * 4 + 3] = fmaf(nv.w, nw_s[q * 4 + 3], L[q * 4 + 3]);
        }

        // top-8 (strict >, lowest index wins ties)
        float best[KSEL];
        int bid[KSEL];
        unsigned long long used = 0ull;
#pragma unroll
        for (int k = 0; k < KSEL; k++) {
            float mv = -INFINITY;
            int mi = 0;
#pragma unroll
            for (int e = 0; e < 64; e++) {
                bool ok = !((used >> e) & 1ull);
                if (ok && L[e] > mv) { mv = L[e]; mi = e; }
            }
            used |= 1ull << mi;
            best[k] = mv;
            bid[k] = mi;
        }
        float m0 = best[0];
        float ss = 0.f;
#pragma unroll
        for (int k = 0; k < KSEL; k++) ss += __expf(best[k] - m0);
        float inv = 1.f / ss;

        float4 z = {0.f, 0.f, 0.f, 0.f};
        float4* ow = (float4*)(out_w + (size_t)(base + r) * NEXP);
#pragma unroll
        for (int q = 0; q < 16; q++) ow[q] = z;
#pragma unroll
        for (int k = 0; k < KSEL; k++) {
            out_w[(size_t)(base + r) * NEXP + bid[k]] = __expf(best[k] - m0) * inv;
            out_ids[(size_t)(base + r) * KSEL + k] = (float)bid[k];
        }
    }
    __syncthreads();
    if (tid < NEXP)
        g_part[blockIdx.x * NEXP + tid] =
            wsum[0][tid] + wsum[1][tid] + wsum[2][tid] + wsum[3][tid];
}

__global__ void loss_kernel(int nBlocks, int N, float* __restrict__ out_loss)
{
    __shared__ double red[256];
    const int t = threadIdx.x;
    const int e = t & 63, g = t >> 6;
    double s = 0.0;
    for (int b = g; b < nBlocks; b += 4) s += (double)g_part[b * NEXP + e];
    red[t] = s;
    __syncthreads();
    if (t < 64) {
        double v = red[e] + red[64 + e] + red[128 + e] + red[192 + e];
        double d = v / (double)N - 1.0 / 64.0;
        red[t] = d * d;
    }
    __syncthreads();
    for (int off = 32; off >= 1; off >>= 1) {
        if (t < off) red[t] += red[t + off];
        __syncthreads();
    }
    if (t == 0) *out_loss = (float)(red[0] / 64.0 * 0.01);
}

extern "C" void kernel_launch(void* const* d_in, const int* in_sizes, int n_in,
                              void* d_out, int out_size)
{
    const float* x     = (const float*)d_in[0];  // [N, 1024]
    const float* w     = (const float*)d_in[1];  // [64, 1024]
    const float* nw    = (const float*)d_in[2];  // [64]
    const float* noise = (const float*)d_in[3];  // [N, 64]

    int N = in_sizes[3] / NEXP;
    int nBlocks = N / MTILE;

    float* out      = (float*)d_out;
    float* out_w    = out;                                        // [N, 64]
    float* out_ids  = out + (size_t)N * NEXP;                     // [N, 8]
    float* out_loss = out + (size_t)N * NEXP + (size_t)N * KSEL;  // [1]

    gate_kernel<<<nBlocks, 512>>>(x, w, nw, noise, out_w, out_ids);
    loss_kernel<<<1, 256>>>(nBlocks, N, out_loss);
}

// round 8
// speedup vs baseline: 1.4753x; 1.0972x over previous
#include <cuda_runtime.h>
#include <cuda_fp16.h>
#include <math.h>
#include <stdint.h>

#define NEXP 64
#define KSEL 8
#define DDIM 1024
#define MTILE 128
#define NCHUNK 32          // K chunks of 32 (2 mma k-steps of 16)
#define MAXBLK 512
#define S11 2048.0f               // 2^11
#define I11 4.8828125e-4f         // 2^-11
#define STEP_STRIDE 1024          // words per k-step in Bfrag: 2 comps x 8 tiles x 64

__device__ float g_part[MAXBLK * NEXP];
// w pre-split into fp16 h/l planes, fragment-native order:
// word offset = (ch*2+step)*1024 + comp*512 + tile*64 + lane*2 + slot
__device__ uint32_t Bfrag[NCHUNK * 2 * 2 * 8 * 64];

__device__ __forceinline__ uint32_t h2u(half2 h) {
    return *reinterpret_cast<uint32_t*>(&h);
}

// 2-level split: v = h + l*2^-11 + r, |r| ~ 2^-24 |v|
__device__ __forceinline__ void split2(float2 v, uint32_t& h, uint32_t& l) {
    half2 hh = __float22half2_rn(v);
    float2 hb = __half22float2(hh);
    half2 ll = __float22half2_rn(
        make_float2((v.x - hb.x) * S11, (v.y - hb.y) * S11));
    h = h2u(hh);
    l = h2u(ll);
}

// chained accumulate (used only for the 2^-11-scaled correction terms)
#define MMA_F16_ACC(cc, a, b0, b1)                                             \
    asm volatile(                                                              \
        "mma.sync.aligned.m16n8k16.row.col.f32.f16.f16.f32 "                   \
        "{%0,%1,%2,%3},{%4,%5,%6,%7},{%8,%9},{%0,%1,%2,%3};"                   \
        : "+f"((cc)[0]), "+f"((cc)[1]), "+f"((cc)[2]), "+f"((cc)[3])           \
        : "r"((a)[0]), "r"((a)[1]), "r"((a)[2]), "r"((a)[3]),                  \
          "r"(b0), "r"(b1))

// fresh accumulator: D = A*B + 0 — avoids tensor-core RZ accumulation bias
#define MMA_F16_NEW(dd, a, b0, b1)                                             \
    asm volatile(                                                              \
        "mma.sync.aligned.m16n8k16.row.col.f32.f16.f16.f32 "                   \
        "{%0,%1,%2,%3},{%4,%5,%6,%7},{%8,%9},{%10,%11,%12,%13};"               \
        : "=f"((dd)[0]), "=f"((dd)[1]), "=f"((dd)[2]), "=f"((dd)[3])           \
        : "r"((a)[0]), "r"((a)[1]), "r"((a)[2]), "r"((a)[3]),                  \
          "r"(b0), "r"(b1),                                                    \
          "f"(0.0f), "f"(0.0f), "f"(0.0f), "f"(0.0f))

// ---- precompute: split w into Bfrag (fragment-native, h/l planes) ----
__global__ void wsplit_kernel(const float* __restrict__ w)
{
    int idx = blockIdx.x * 256 + threadIdx.x;    // 0..32767 = (n, kpair)
    int n = idx >> 9;                            // expert
    int kp = idx & 511;                          // k/2
    float2 v = *(const float2*)(w + (size_t)n * DDIM + kp * 2);
    uint32_t h, l;
    split2(v, h, l);
    int k = kp * 2;
    int ch = k >> 5, win = k & 31;
    int s = win >> 4, kk = win & 15;
    int sl = kk >> 3, q = (kk & 7) >> 1;
    int tile = n >> 3, lane = (n & 7) * 4 + q;
    uint32_t base = (uint32_t)(ch * 2 + s) * STEP_STRIDE + tile * 64 + lane * 2 + sl;
    Bfrag[base]       = h;   // comp 0 (h plane)
    Bfrag[base + 512] = l;   // comp 1 (l plane), comp stride = 8*64
}

__global__ void __launch_bounds__(512) gate_kernel(
    const float* __restrict__ x,
    const float* __restrict__ nw, const float* __restrict__ noise,
    float* __restrict__ out_w, float* __restrict__ out_ids)
{
    __shared__ __align__(16) float U[128 * 65];  // epilogue canvas only
    __shared__ float nw_s[NEXP];
    __shared__ float wsum[4][NEXP];

    const int tid    = threadIdx.x;
    const int wid    = tid >> 5;
    const int lane   = tid & 31;
    const int quad   = lane & 3;
    const int r0     = lane >> 2;
    const int rowgrp = wid >> 1;    // 0..7 -> rows rowgrp*16..+15
    const int eg     = wid & 1;     // expert half: tiles eg*4..eg*4+3
    const int base   = blockIdx.x * MTILE;

    if (tid < NEXP) nw_s[tid] = nw[tid];

    const float* pA  = x + (size_t)(base + rowgrp * 16 + r0) * DDIM + quad * 2;
    const float* pA8 = pA + 8 * DDIM;
    // B fragment pointer for this warp (tiles eg*4..+3), lane-resolved
    const uint32_t* const Bp = Bfrag + (uint32_t)(eg * 4) * 64 + lane * 2;

    float c0[4][4], c1[4][4];
#pragma unroll
    for (int t = 0; t < 4; t++)
#pragma unroll
        for (int i = 0; i < 4; i++) { c0[t][i] = 0.f; c1[t][i] = 0.f; }

// Raw A chunk: per kstep s, 4 float2 pairs in fragment order
#define LDA(ch, a) do {                                                        \
    _Pragma("unroll")                                                          \
    for (int _s2 = 0; _s2 < 2; _s2++) {                                        \
        *(float2*)&(a)[_s2 * 8 + 0] = *(const float2*)(pA  + (ch) * 32 + _s2 * 16);     \
        *(float2*)&(a)[_s2 * 8 + 2] = *(const float2*)(pA8 + (ch) * 32 + _s2 * 16);     \
        *(float2*)&(a)[_s2 * 8 + 4] = *(const float2*)(pA  + (ch) * 32 + _s2 * 16 + 8); \
        *(float2*)&(a)[_s2 * 8 + 6] = *(const float2*)(pA8 + (ch) * 32 + _s2 * 16 + 8); \
    }                                                                          \
} while (0)

#define CHUNK_BODY(ch, aC, aN) do {                                            \
    if ((ch) + 1 < NCHUNK) LDA((ch) + 1, aN);                                  \
    _Pragma("unroll")                                                          \
    for (int _s = 0; _s < 2; _s++) {                                           \
        uint32_t ah[4], al[4];                                                 \
        _Pragma("unroll")                                                      \
        for (int _i = 0; _i < 4; _i++)                                         \
            split2(*(float2*)&(aC)[_s * 8 + _i * 2], ah[_i], al[_i]);          \
        const uint32_t* bp = Bp + ((uint32_t)(ch) * 2 + _s) * STEP_STRIDE;     \
        _Pragma("unroll")                                                      \
        for (int _t = 0; _t < 4; _t++) {                                       \
            uint2 bh = *(const uint2*)(bp + _t * 64);                          \
            uint2 bl = *(const uint2*)(bp + _t * 64 + 512);                    \
            float dd[4];                                                       \
            MMA_F16_NEW(dd, ah, bh.x, bh.y);                                   \
            MMA_F16_ACC(c1[_t], ah, bl.x, bl.y);                               \
            MMA_F16_ACC(c1[_t], al, bh.x, bh.y);                               \
            c0[_t][0] += dd[0];                                                \
            c0[_t][1] += dd[1];                                                \
            c0[_t][2] += dd[2];                                                \
            c0[_t][3] += dd[3];                                                \
        }                                                                      \
    }                                                                          \
} while (0)

    // ---- main loop: no smem, no barriers; ping-pong A in registers ----
    float aCur[16], aNxt[16];
    LDA(0, aCur);
#pragma unroll 1
    for (int cc = 0; cc < NCHUNK; cc += 2) {
        CHUNK_BODY(cc, aCur, aNxt);
        CHUNK_BODY(cc + 1, aNxt, aCur);
    }

    // ---- combine levels, dump to L[128][65] ----
    {
        int rA = rowgrp * 16 + r0;
#pragma unroll
        for (int t = 0; t < 4; t++) {
            int cb = (eg * 4 + t) * 8 + 2 * quad;
#pragma unroll
            for (int i = 0; i < 4; i++) {
                float v = fmaf(c1[t][i], I11, c0[t][i]);
                int rr = rA + (i >> 1) * 8;
                U[rr * 65 + cb + (i & 1)] = v;
            }
        }
    }
    __syncthreads();

    // ---- epilogue: threads 0..127 own one row each ----
    if (tid < 128) {
        const int r = tid;
        float L[64];
#pragma unroll
        for (int e = 0; e < 64; e++) L[e] = U[r * 65 + e];

        float m = -INFINITY;
#pragma unroll
        for (int e = 0; e < 64; e++) m = fmaxf(m, L[e]);
        float s = 0.f;
#pragma unroll
        for (int e = 0; e < 64; e++) s += __expf(L[e] - m);
        float sinv = 1.f / s;

        // per-expert column sums over this warp's 32 rows (deterministic)
#pragma unroll
        for (int e = 0; e < 64; e++) {
            float v = __expf(L[e] - m) * sinv;
            v += __shfl_xor_sync(0xffffffffu, v, 16);
            v += __shfl_xor_sync(0xffffffffu, v, 8);
            v += __shfl_xor_sync(0xffffffffu, v, 4);
            v += __shfl_xor_sync(0xffffffffu, v, 2);
            v += __shfl_xor_sync(0xffffffffu, v, 1);
            if ((e & 31) == lane) wsum[wid][e] = v;
        }

        // noisy logits
        const float4* np = (const float4*)(noise + (size_t)(base + r) * NEXP);
#pragma unroll
        for (int q = 0; q < 16; q++) {
            float4 nv = np[q];
            L[q * 4 + 0] = fmaf(nv.x, nw_s[q * 4 + 0], L[q * 4 + 0]);
            L[q * 4 + 1] = fmaf(nv.y, nw_s[q * 4 + 1], L[q * 4 + 1]);
            L[q * 4 + 2] = fmaf(nv.z, nw_s[q * 4 + 2], L[q * 4 + 2]);
            L[q * 4 + 3] = fmaf(nv.w, nw_s[q * 4 + 3], L[q * 4 + 3]);
        }

        // top-8 (strict >, lowest index wins ties)
        float best[KSEL];
        int bid[KSEL];
        unsigned long long used = 0ull;
#pragma unroll
        for (int k = 0; k < KSEL; k++) {
            float mv = -INFINITY;
            int mi = 0;
#pragma unroll
            for (int e = 0; e < 64; e++) {
                bool ok = !((used >> e) & 1ull);
                if (ok && L[e] > mv) { mv = L[e]; mi = e; }
            }
            used |= 1ull << mi;
            best[k] = mv;
            bid[k] = mi;
        }
        float m0 = best[0];
        float ss = 0.f;
#pragma unroll
        for (int k = 0; k < KSEL; k++) ss += __expf(best[k] - m0);
        float inv = 1.f / ss;

        float4 z = {0.f, 0.f, 0.f, 0.f};
        float4* ow = (float4*)(out_w + (size_t)(base + r) * NEXP);
#pragma unroll
        for (int q = 0; q < 16; q++) ow[q] = z;
#pragma unroll
        for (int k = 0; k < KSEL; k++) {
            out_w[(size_t)(base + r) * NEXP + bid[k]] = __expf(best[k] - m0) * inv;
            out_ids[(size_t)(base + r) * KSEL + k] = (float)bid[k];
        }
    }
    __syncthreads();
    if (tid < NEXP)
        g_part[blockIdx.x * NEXP + tid] =
            wsum[0][tid] + wsum[1][tid] + wsum[2][tid] + wsum[3][tid];
}

__global__ void __launch_bounds__(1024) loss_kernel(
    int nBlocks, int N, float* __restrict__ out_loss)
{
    __shared__ double red[1024];
    const int t = threadIdx.x;
    const int e = t & 63, g = t >> 6;  // 16 partials per expert
    double s = 0.0;
    for (int b = g; b < nBlocks; b += 16) s += (double)g_part[b * NEXP + e];
    red[t] = s;
    __syncthreads();
    for (int off = 512; off >= 64; off >>= 1) {
        if (t < off) red[t] += red[t + off];
        __syncthreads();
    }
    if (t < 64) {
        double d = red[t] / (double)N - 1.0 / 64.0;
        red[t] = d * d;
    }
    __syncthreads();
    for (int off = 32; off >= 1; off >>= 1) {
        if (t < off) red[t] += red[t + off];
        __syncthreads();
    }
    if (t == 0) *out_loss = (float)(red[0] / 64.0 * 0.01);
}

extern "C" void kernel_launch(void* const* d_in, const int* in_sizes, int n_in,
                              void* d_out, int out_size)
{
    const float* x     = (const float*)d_in[0];  // [N, 1024]
    const float* w     = (const float*)d_in[1];  // [64, 1024]
    const float* nw    = (const float*)d_in[2];  // [64]
    const float* noise = (const float*)d_in[3];  // [N, 64]

    int N = in_sizes[3] / NEXP;
    int nBlocks = N / MTILE;

    float* out      = (float*)d_out;
    float* out_w    = out;                                        // [N, 64]
    float* out_ids  = out + (size_t)N * NEXP;                     // [N, 8]
    float* out_loss = out + (size_t)N * NEXP + (size_t)N * KSEL;  // [1]

    wsplit_kernel<<<128, 256>>>(w);
    gate_kernel<<<nBlocks, 512>>>(x, nw, noise, out_w, out_ids);
    loss_kernel<<<1, 1024>>>(nBlocks, N, out_loss);
}